// round 1
// baseline (speedup 1.0000x reference)
#include <cuda_runtime.h>
#include <cuda_bf16.h>

// GCN: 2-layer graph conv, N=100000 nodes, E edges, 128 -> 32 -> 32.
// Pipeline (all on default stream, graph-capturable, no allocs):
//   1. zero scratch (deg, agg1, agg2)
//   2. degrees via RED                  (3.2M scalar red.f32)
//   3. norms = rsqrt(max(deg,1))
//   4. h = feat @ W1                    (smem GEMM, 100K x 128 x 32)
//   5. agg1 += h[src]*norm_out[src]     (red.global.add.v4.f32, table fits L2)
//   6. t = relu(agg1*norm_in + b1); h = t @ W2
//   7. agg2 += h[src]*norm_out[src]
//   8. out = agg2*norm_in + b2

#define MAXN 100000

__device__ float g_deg_out[MAXN];
__device__ float g_deg_in[MAXN];
__device__ float g_norm_out[MAXN];
__device__ float g_norm_in[MAXN];
__device__ float g_h[MAXN * 32];     // projected features (reused for both layers)
__device__ float g_agg1[MAXN * 32];
__device__ float g_agg2[MAXN * 32];

__device__ __forceinline__ void red_add_v4(float* addr, float4 v) {
    asm volatile("red.global.add.v4.f32 [%0], {%1, %2, %3, %4};"
                 :: "l"(addr), "f"(v.x), "f"(v.y), "f"(v.z), "f"(v.w)
                 : "memory");
}

// ---------------------------------------------------------------- zero scratch
__global__ void zero_kernel(int n) {
    int i = blockIdx.x * blockDim.x + threadIdx.x;
    if (i < n) { g_deg_out[i] = 0.f; g_deg_in[i] = 0.f; }
    if (i < n * 32) { g_agg1[i] = 0.f; g_agg2[i] = 0.f; }
}

// ---------------------------------------------------------------- degrees
__global__ void degree_kernel(const int* __restrict__ src,
                              const int* __restrict__ dst, int E) {
    int e = blockIdx.x * blockDim.x + threadIdx.x;
    if (e < E) {
        atomicAdd(&g_deg_out[src[e]], 1.f);   // emitted as RED (result unused)
        atomicAdd(&g_deg_in[dst[e]], 1.f);
    }
}

// ---------------------------------------------------------------- norms
__global__ void norm_kernel(int n) {
    int i = blockIdx.x * blockDim.x + threadIdx.x;
    if (i < n) {
        g_norm_out[i] = rsqrtf(fmaxf(g_deg_out[i], 1.f));
        g_norm_in[i]  = rsqrtf(fmaxf(g_deg_in[i], 1.f));
    }
}

// ---------------------------------------------------------------- h = feat @ W1
// 256 threads: 32 rows/block, 8 threads/row, each thread -> 4 output cols.
__global__ void gemm1_kernel(const float* __restrict__ feat,
                             const float* __restrict__ W1, int n) {
    __shared__ float sW[128 * 32];
    __shared__ float sF[32 * 129];          // pad to kill bank conflicts
    int t = threadIdx.x;
    for (int i = t; i < 128 * 32; i += 256) sW[i] = W1[i];
    int row0 = blockIdx.x * 32;
    for (int i = t; i < 32 * 128; i += 256) {
        int r = i >> 7, c = i & 127;
        int gr = row0 + r;
        sF[r * 129 + c] = (gr < n) ? feat[gr * 128 + c] : 0.f;
    }
    __syncthreads();
    int r = t >> 3, cg = t & 7;
    float4 acc = make_float4(0.f, 0.f, 0.f, 0.f);
    const float* fr = &sF[r * 129];
    #pragma unroll
    for (int k = 0; k < 128; k++) {
        float f = fr[k];
        float4 w = *(const float4*)&sW[k * 32 + cg * 4];
        acc.x += f * w.x; acc.y += f * w.y; acc.z += f * w.z; acc.w += f * w.w;
    }
    int gr = row0 + r;
    if (gr < n) *(float4*)&g_h[gr * 32 + cg * 4] = acc;
}

// ---------------------------------------------------------------- edge pass
// 8 threads per edge, each moves a float4: agg[dst] += h[src] * norm_out[src].
__global__ void edge_kernel(const int* __restrict__ src,
                            const int* __restrict__ dst, int E, int layer) {
    int tid = blockIdx.x * blockDim.x + threadIdx.x;
    int e = tid >> 3;
    if (e >= E) return;
    int q = tid & 7;
    int s = __ldg(&src[e]);
    int d = __ldg(&dst[e]);
    float ns = g_norm_out[s];
    float4 v = *(const float4*)&g_h[s * 32 + q * 4];
    v.x *= ns; v.y *= ns; v.z *= ns; v.w *= ns;
    float* agg = (layer == 0) ? g_agg1 : g_agg2;
    red_add_v4(&agg[d * 32 + q * 4], v);
}

// ---------------------------------------------------------------- mid: relu + GEMM2
// t = relu(agg1*norm_in + b1); g_h = t @ W2
__global__ void mid_kernel(const float* __restrict__ b1,
                           const float* __restrict__ W2, int n) {
    __shared__ float sW[32 * 32];
    __shared__ float sT[32 * 33];
    int t = threadIdx.x;
    for (int i = t; i < 32 * 32; i += 256) sW[i] = W2[i];
    int row0 = blockIdx.x * 32;
    for (int i = t; i < 32 * 32; i += 256) {
        int r = i >> 5, c = i & 31;
        int gr = row0 + r;
        float v = 0.f;
        if (gr < n) {
            v = g_agg1[gr * 32 + c] * g_norm_in[gr] + __ldg(&b1[c]);
            v = fmaxf(v, 0.f);
        }
        sT[r * 33 + c] = v;
    }
    __syncthreads();
    int r = t >> 3, cg = t & 7;
    float4 acc = make_float4(0.f, 0.f, 0.f, 0.f);
    #pragma unroll
    for (int k = 0; k < 32; k++) {
        float f = sT[r * 33 + k];
        float4 w = *(const float4*)&sW[k * 32 + cg * 4];
        acc.x += f * w.x; acc.y += f * w.y; acc.z += f * w.z; acc.w += f * w.w;
    }
    int gr = row0 + r;
    if (gr < n) *(float4*)&g_h[gr * 32 + cg * 4] = acc;
}

// ---------------------------------------------------------------- output
__global__ void out_kernel(const float* __restrict__ b2,
                           float* __restrict__ out, int n) {
    int idx = blockIdx.x * blockDim.x + threadIdx.x;
    if (idx >= n * 8) return;
    int row = idx >> 3, q = idx & 7;
    float4 v = *(const float4*)&g_agg2[row * 32 + q * 4];
    float ni = g_norm_in[row];
    float4 b = *(const float4*)&b2[q * 4];
    v.x = v.x * ni + b.x;
    v.y = v.y * ni + b.y;
    v.z = v.z * ni + b.z;
    v.w = v.w * ni + b.w;
    *(float4*)&out[row * 32 + q * 4] = v;
}

extern "C" void kernel_launch(void* const* d_in, const int* in_sizes, int n_in,
                              void* d_out, int out_size) {
    const float* feat = (const float*)d_in[0];
    const float* W1   = (const float*)d_in[1];
    const float* b1   = (const float*)d_in[2];
    const float* W2   = (const float*)d_in[3];
    const float* b2   = (const float*)d_in[4];
    const int*   src  = (const int*)d_in[5];
    const int*   dst  = (const int*)d_in[6];
    float* out = (float*)d_out;

    int n = in_sizes[0] / 128;
    int E = in_sizes[5];

    const int B = 256;
    long ethreads = (long)E * 8;

    zero_kernel  <<<(n * 32 + B - 1) / B, B>>>(n);
    degree_kernel<<<(E + B - 1) / B, B>>>(src, dst, E);
    norm_kernel  <<<(n + B - 1) / B, B>>>(n);
    gemm1_kernel <<<(n + 31) / 32, 256>>>(feat, W1, n);
    edge_kernel  <<<(int)((ethreads + B - 1) / B), B>>>(src, dst, E, 0);
    mid_kernel   <<<(n + 31) / 32, 256>>>(b1, W2, n);
    edge_kernel  <<<(int)((ethreads + B - 1) / B), B>>>(src, dst, E, 1);
    out_kernel   <<<(n * 8 + B - 1) / B, B>>>(b2, out, n);
}

// round 2
// speedup vs baseline: 1.2813x; 1.2813x over previous
#include <cuda_runtime.h>
#include <cuda_bf16.h>

// GCN: 2-layer graph conv, N=100000, E=1.6M, 128 -> 32 -> 32.
// Round 2: register-blocked GEMM1 (FMA-bound, not LDS-bound), norm_out fused
// into GEMM epilogues so edge passes are pure gather + red.v4 scatter.

#define MAXN 100000

__device__ float  g_deg_out[MAXN];
__device__ float  g_deg_in[MAXN];
__device__ float  g_norm_out[MAXN];
__device__ float  g_norm_in[MAXN];
__device__ float4 g_h[MAXN * 8];      // projected features, pre-scaled by norm_out
__device__ float  g_agg1[MAXN * 32];
__device__ float  g_agg2[MAXN * 32];

__device__ __forceinline__ void red_add_v4(float* addr, float4 v) {
    asm volatile("red.global.add.v4.f32 [%0], {%1, %2, %3, %4};"
                 :: "l"(addr), "f"(v.x), "f"(v.y), "f"(v.z), "f"(v.w)
                 : "memory");
}

// ---------------------------------------------------------------- zero scratch
__global__ void zero_kernel(int n) {
    int i = blockIdx.x * blockDim.x + threadIdx.x;
    if (i < n) { g_deg_out[i] = 0.f; g_deg_in[i] = 0.f; }
    if (i < n * 8) {
        float4 z = make_float4(0.f, 0.f, 0.f, 0.f);
        ((float4*)g_agg1)[i] = z;
        ((float4*)g_agg2)[i] = z;
    }
}

// ---------------------------------------------------------------- degrees
__global__ void degree_kernel(const int* __restrict__ src,
                              const int* __restrict__ dst, int E) {
    int e = blockIdx.x * blockDim.x + threadIdx.x;
    if (e < E) {
        atomicAdd(&g_deg_out[src[e]], 1.f);   // RED (result unused)
        atomicAdd(&g_deg_in[dst[e]], 1.f);
    }
}

// ---------------------------------------------------------------- norms
__global__ void norm_kernel(int n) {
    int i = blockIdx.x * blockDim.x + threadIdx.x;
    if (i < n) {
        g_norm_out[i] = rsqrtf(fmaxf(g_deg_out[i], 1.f));
        g_norm_in[i]  = rsqrtf(fmaxf(g_deg_in[i], 1.f));
    }
}

// ---------------------------------------------------------------- GEMM1
// g_h[row] = (feat[row] @ W1) * norm_out[row]
// Block: 64 rows x 32 cols, 256 threads. Thread (rt, cg): rows {rt, rt+32},
// cols cg*4..cg*4+3. k unrolled x4 via float4. XOR swizzle on feature tile.
__global__ void gemm1_kernel(const float* __restrict__ feat,
                             const float* __restrict__ W1, int n) {
    __shared__ float4 sW[128 * 8];   // [k][colgroup]   16 KB
    __shared__ float4 sF[64 * 32];   // [row][k4 ^ (row&7)]  32 KB
    int t = threadIdx.x;
    for (int i = t; i < 128 * 8; i += 256) sW[i] = ((const float4*)W1)[i];
    int row0 = blockIdx.x * 64;
    for (int i = t; i < 64 * 32; i += 256) {
        int r = i >> 5, k4 = i & 31;
        int gr = row0 + r;
        float4 v = make_float4(0.f, 0.f, 0.f, 0.f);
        if (gr < n) v = ((const float4*)feat)[gr * 32 + k4];
        sF[r * 32 + (k4 ^ (r & 7))] = v;
    }
    __syncthreads();

    int rt = t >> 3, cg = t & 7;
    int sw = rt & 7;
    const float4* f0p = &sF[rt * 32];
    const float4* f1p = &sF[(rt + 32) * 32];
    float4 a0 = make_float4(0.f, 0.f, 0.f, 0.f);
    float4 a1 = make_float4(0.f, 0.f, 0.f, 0.f);

    #pragma unroll 8
    for (int k4 = 0; k4 < 32; k4++) {
        float4 f0 = f0p[k4 ^ sw];
        float4 f1 = f1p[k4 ^ sw];
        float4 w0 = sW[(k4 * 4 + 0) * 8 + cg];
        float4 w1 = sW[(k4 * 4 + 1) * 8 + cg];
        float4 w2 = sW[(k4 * 4 + 2) * 8 + cg];
        float4 w3 = sW[(k4 * 4 + 3) * 8 + cg];

        a0.x += f0.x*w0.x; a0.y += f0.x*w0.y; a0.z += f0.x*w0.z; a0.w += f0.x*w0.w;
        a0.x += f0.y*w1.x; a0.y += f0.y*w1.y; a0.z += f0.y*w1.z; a0.w += f0.y*w1.w;
        a0.x += f0.z*w2.x; a0.y += f0.z*w2.y; a0.z += f0.z*w2.z; a0.w += f0.z*w2.w;
        a0.x += f0.w*w3.x; a0.y += f0.w*w3.y; a0.z += f0.w*w3.z; a0.w += f0.w*w3.w;

        a1.x += f1.x*w0.x; a1.y += f1.x*w0.y; a1.z += f1.x*w0.z; a1.w += f1.x*w0.w;
        a1.x += f1.y*w1.x; a1.y += f1.y*w1.y; a1.z += f1.y*w1.z; a1.w += f1.y*w1.w;
        a1.x += f1.z*w2.x; a1.y += f1.z*w2.y; a1.z += f1.z*w2.z; a1.w += f1.z*w2.w;
        a1.x += f1.w*w3.x; a1.y += f1.w*w3.y; a1.z += f1.w*w3.z; a1.w += f1.w*w3.w;
    }

    int gr0 = row0 + rt;
    int gr1 = row0 + rt + 32;
    if (gr0 < n) {
        float ns = g_norm_out[gr0];
        a0.x *= ns; a0.y *= ns; a0.z *= ns; a0.w *= ns;
        g_h[gr0 * 8 + cg] = a0;
    }
    if (gr1 < n) {
        float ns = g_norm_out[gr1];
        a1.x *= ns; a1.y *= ns; a1.z *= ns; a1.w *= ns;
        g_h[gr1 * 8 + cg] = a1;
    }
}

// ---------------------------------------------------------------- edge pass
// agg[dst] += g_h[src]  (g_h pre-scaled by norm_out). 8 threads/edge, float4 each.
template <int LAYER>
__global__ void edge_kernel(const int* __restrict__ src,
                            const int* __restrict__ dst, int E) {
    int tid = blockIdx.x * blockDim.x + threadIdx.x;
    int e = tid >> 3;
    if (e >= E) return;
    int q = tid & 7;
    int s = __ldg(&src[e]);
    int d = __ldg(&dst[e]);
    float4 v = g_h[s * 8 + q];
    float* agg = (LAYER == 0) ? g_agg1 : g_agg2;
    red_add_v4(&agg[d * 32 + q * 4], v);
}

// ---------------------------------------------------------------- mid
// t = relu(agg1*norm_in + b1);  g_h = (t @ W2) * norm_out
__global__ void mid_kernel(const float* __restrict__ b1,
                           const float* __restrict__ W2, int n) {
    __shared__ float sW[32 * 32];
    __shared__ float sT[32 * 33];
    int t = threadIdx.x;
    for (int i = t; i < 32 * 32; i += 256) sW[i] = W2[i];
    int row0 = blockIdx.x * 32;
    for (int i = t; i < 32 * 32; i += 256) {
        int r = i >> 5, c = i & 31;
        int gr = row0 + r;
        float v = 0.f;
        if (gr < n) {
            v = g_agg1[gr * 32 + c] * g_norm_in[gr] + __ldg(&b1[c]);
            v = fmaxf(v, 0.f);
        }
        sT[r * 33 + c] = v;
    }
    __syncthreads();
    int r = t >> 3, cg = t & 7;
    float4 acc = make_float4(0.f, 0.f, 0.f, 0.f);
    #pragma unroll
    for (int k = 0; k < 32; k++) {
        float f = sT[r * 33 + k];
        float4 w = *(const float4*)&sW[k * 32 + cg * 4];
        acc.x += f * w.x; acc.y += f * w.y; acc.z += f * w.z; acc.w += f * w.w;
    }
    int gr = row0 + r;
    if (gr < n) {
        float ns = g_norm_out[gr];
        acc.x *= ns; acc.y *= ns; acc.z *= ns; acc.w *= ns;
        g_h[gr * 8 + cg] = acc;
    }
}

// ---------------------------------------------------------------- output
__global__ void out_kernel(const float* __restrict__ b2,
                           float* __restrict__ out, int n) {
    int idx = blockIdx.x * blockDim.x + threadIdx.x;
    if (idx >= n * 8) return;
    int row = idx >> 3, q = idx & 7;
    float4 v = *(const float4*)&g_agg2[row * 32 + q * 4];
    float ni = g_norm_in[row];
    float4 b = *(const float4*)&b2[q * 4];
    v.x = v.x * ni + b.x;
    v.y = v.y * ni + b.y;
    v.z = v.z * ni + b.z;
    v.w = v.w * ni + b.w;
    *(float4*)&out[row * 32 + q * 4] = v;
}

extern "C" void kernel_launch(void* const* d_in, const int* in_sizes, int n_in,
                              void* d_out, int out_size) {
    const float* feat = (const float*)d_in[0];
    const float* W1   = (const float*)d_in[1];
    const float* b1   = (const float*)d_in[2];
    const float* W2   = (const float*)d_in[3];
    const float* b2   = (const float*)d_in[4];
    const int*   src  = (const int*)d_in[5];
    const int*   dst  = (const int*)d_in[6];
    float* out = (float*)d_out;

    int n = in_sizes[0] / 128;
    int E = in_sizes[5];

    const int B = 256;
    long ethreads = (long)E * 8;
    int eblocks = (int)((ethreads + B - 1) / B);

    zero_kernel   <<<(n * 8 + B - 1) / B, B>>>(n);
    degree_kernel <<<(E + B - 1) / B, B>>>(src, dst, E);
    norm_kernel   <<<(n + B - 1) / B, B>>>(n);
    gemm1_kernel  <<<(n + 63) / 64, 256>>>(feat, W1, n);
    edge_kernel<0><<<eblocks, B>>>(src, dst, E);
    mid_kernel    <<<(n + 31) / 32, 256>>>(b1, W2, n);
    edge_kernel<1><<<eblocks, B>>>(src, dst, E);
    out_kernel    <<<(n * 8 + B - 1) / B, B>>>(b2, out, n);
}

// round 3
// speedup vs baseline: 1.5714x; 1.2264x over previous
#include <cuda_runtime.h>
#include <cuda_bf16.h>

// GCN: 2-layer graph conv, N=100000, E=1.6M, 128 -> 32 -> 32.
// Round 3:
//  - gemm1: 128 rows/block, 4 rows/thread -> FFMA:LDS.128 = 8:1 (crossbar/FMA balanced)
//  - mid:   same register-blocked structure (k=32)
//  - degree/norm chain overlapped with gemm1 via event fork-join (graph-capture safe)
//  - scale_h applies norm_out to h after the join (mid fuses norm_out itself)

#define MAXN 100000

__device__ float  g_deg_out[MAXN];
__device__ float  g_deg_in[MAXN];
__device__ float  g_norm_out[MAXN];
__device__ float  g_norm_in[MAXN];
__device__ float4 g_h[MAXN * 8];      // projected features (scaled by norm_out before edge pass)
__device__ float  g_agg1[MAXN * 32];
__device__ float  g_agg2[MAXN * 32];

__device__ __forceinline__ void red_add_v4(float* addr, float4 v) {
    asm volatile("red.global.add.v4.f32 [%0], {%1, %2, %3, %4};"
                 :: "l"(addr), "f"(v.x), "f"(v.y), "f"(v.z), "f"(v.w)
                 : "memory");
}

// ---------------------------------------------------------------- zero scratch
__global__ void zero_kernel(int n) {
    int i = blockIdx.x * blockDim.x + threadIdx.x;
    if (i < n) { g_deg_out[i] = 0.f; g_deg_in[i] = 0.f; }
    if (i < n * 8) {
        float4 z = make_float4(0.f, 0.f, 0.f, 0.f);
        ((float4*)g_agg1)[i] = z;
        ((float4*)g_agg2)[i] = z;
    }
}

// ---------------------------------------------------------------- degrees
__global__ void degree_kernel(const int* __restrict__ src,
                              const int* __restrict__ dst, int E) {
    int e = blockIdx.x * blockDim.x + threadIdx.x;
    if (e < E) {
        atomicAdd(&g_deg_out[src[e]], 1.f);   // RED (result unused)
        atomicAdd(&g_deg_in[dst[e]], 1.f);
    }
}

// ---------------------------------------------------------------- norms
__global__ void norm_kernel(int n) {
    int i = blockIdx.x * blockDim.x + threadIdx.x;
    if (i < n) {
        g_norm_out[i] = rsqrtf(fmaxf(g_deg_out[i], 1.f));
        g_norm_in[i]  = rsqrtf(fmaxf(g_deg_in[i], 1.f));
    }
}

// ---------------------------------------------------------------- GEMM1
// g_h[row] = feat[row] @ W1   (unscaled; scale_h applies norm_out after join)
// 256 threads, 128 rows x 32 cols per block, 4 rows/thread.
// Dynamic smem: sW 128x8 float4 (16KB) + sF 128x32 float4 XOR-swizzled (64KB).
__global__ __launch_bounds__(256) void gemm1_kernel(const float* __restrict__ feat,
                                                    const float* __restrict__ W1, int n) {
    extern __shared__ float4 dyn[];
    float4* sW = dyn;            // [k=128][cg=8]
    float4* sF = dyn + 1024;     // [row=128][k4=32] swizzled
    int t = threadIdx.x;

    for (int i = t; i < 1024; i += 256) sW[i] = ((const float4*)W1)[i];
    int row0 = blockIdx.x * 128;
    #pragma unroll
    for (int j = 0; j < 16; j++) {
        int i = t + j * 256;
        int r = i >> 5, k4 = i & 31;
        int gr = row0 + r;
        float4 v = make_float4(0.f, 0.f, 0.f, 0.f);
        if (gr < n) v = ((const float4*)feat)[gr * 32 + k4];
        sF[r * 32 + (k4 ^ (r & 7))] = v;
    }
    __syncthreads();

    int rt = t >> 3, cg = t & 7;    // rt 0..31, rows rt, rt+32, rt+64, rt+96
    int sw = rt & 7;
    const float4* fp0 = &sF[(rt +  0) * 32];
    const float4* fp1 = &sF[(rt + 32) * 32];
    const float4* fp2 = &sF[(rt + 64) * 32];
    const float4* fp3 = &sF[(rt + 96) * 32];

    float4 a0 = make_float4(0.f,0.f,0.f,0.f), a1 = a0, a2 = a0, a3 = a0;

    #pragma unroll 4
    for (int k4 = 0; k4 < 32; k4++) {
        float4 f0 = fp0[k4 ^ sw];
        float4 f1 = fp1[k4 ^ sw];
        float4 f2 = fp2[k4 ^ sw];
        float4 f3 = fp3[k4 ^ sw];
        #pragma unroll
        for (int i = 0; i < 4; i++) {
            float4 w = sW[(k4 * 4 + i) * 8 + cg];
            float c0 = (i == 0) ? f0.x : (i == 1) ? f0.y : (i == 2) ? f0.z : f0.w;
            float c1 = (i == 0) ? f1.x : (i == 1) ? f1.y : (i == 2) ? f1.z : f1.w;
            float c2 = (i == 0) ? f2.x : (i == 1) ? f2.y : (i == 2) ? f2.z : f2.w;
            float c3 = (i == 0) ? f3.x : (i == 1) ? f3.y : (i == 2) ? f3.z : f3.w;
            a0.x += c0*w.x; a0.y += c0*w.y; a0.z += c0*w.z; a0.w += c0*w.w;
            a1.x += c1*w.x; a1.y += c1*w.y; a1.z += c1*w.z; a1.w += c1*w.w;
            a2.x += c2*w.x; a2.y += c2*w.y; a2.z += c2*w.z; a2.w += c2*w.w;
            a3.x += c3*w.x; a3.y += c3*w.y; a3.z += c3*w.z; a3.w += c3*w.w;
        }
    }

    int gr;
    gr = row0 + rt;      if (gr < n) g_h[gr * 8 + cg] = a0;
    gr = row0 + rt + 32; if (gr < n) g_h[gr * 8 + cg] = a1;
    gr = row0 + rt + 64; if (gr < n) g_h[gr * 8 + cg] = a2;
    gr = row0 + rt + 96; if (gr < n) g_h[gr * 8 + cg] = a3;
}

// ---------------------------------------------------------------- scale h by norm_out
__global__ void scale_h_kernel(int n) {
    int i = blockIdx.x * blockDim.x + threadIdx.x;
    if (i >= n * 8) return;
    float s = g_norm_out[i >> 3];
    float4 v = g_h[i];
    v.x *= s; v.y *= s; v.z *= s; v.w *= s;
    g_h[i] = v;
}

// ---------------------------------------------------------------- edge pass
// agg[dst] += g_h[src]  (g_h pre-scaled by norm_out). 8 threads/edge, float4 each.
template <int LAYER>
__global__ void edge_kernel(const int* __restrict__ src,
                            const int* __restrict__ dst, int E) {
    int tid = blockIdx.x * blockDim.x + threadIdx.x;
    int e = tid >> 3;
    if (e >= E) return;
    int q = tid & 7;
    int s = __ldg(&src[e]);
    int d = __ldg(&dst[e]);
    float4 v = g_h[s * 8 + q];
    float* agg = (LAYER == 0) ? g_agg1 : g_agg2;
    red_add_v4(&agg[d * 32 + q * 4], v);
}

// ---------------------------------------------------------------- mid
// t = relu(agg1*norm_in + b1);  g_h = (t @ W2) * norm_out
// Same register-blocked structure as gemm1, k=32. 20KB static smem.
__global__ __launch_bounds__(256) void mid_kernel(const float* __restrict__ b1,
                                                  const float* __restrict__ W2, int n) {
    __shared__ float4 sW2[32 * 8];    // [k=32][cg=8]  4KB
    __shared__ float4 sT[128 * 8];    // [row=128][k4=8] swizzled  16KB
    int t = threadIdx.x;
    for (int i = t; i < 256; i += 256) sW2[i] = ((const float4*)W2)[i];
    int row0 = blockIdx.x * 128;
    #pragma unroll
    for (int j = 0; j < 4; j++) {
        int i = t + j * 256;
        int r = i >> 3, k4 = i & 7;
        int gr = row0 + r;
        float4 v = make_float4(0.f, 0.f, 0.f, 0.f);
        if (gr < n) {
            float4 a = ((const float4*)g_agg1)[gr * 8 + k4];
            float ni = g_norm_in[gr];
            float4 b = ((const float4*)b1)[k4];
            v.x = fmaxf(a.x * ni + b.x, 0.f);
            v.y = fmaxf(a.y * ni + b.y, 0.f);
            v.z = fmaxf(a.z * ni + b.z, 0.f);
            v.w = fmaxf(a.w * ni + b.w, 0.f);
        }
        sT[r * 8 + (k4 ^ (r & 7))] = v;
    }
    __syncthreads();

    int rt = t >> 3, cg = t & 7;
    int sw = rt & 7;
    const float4* fp0 = &sT[(rt +  0) * 8];
    const float4* fp1 = &sT[(rt + 32) * 8];
    const float4* fp2 = &sT[(rt + 64) * 8];
    const float4* fp3 = &sT[(rt + 96) * 8];

    float4 a0 = make_float4(0.f,0.f,0.f,0.f), a1 = a0, a2 = a0, a3 = a0;

    #pragma unroll
    for (int k4 = 0; k4 < 8; k4++) {
        float4 f0 = fp0[k4 ^ sw];
        float4 f1 = fp1[k4 ^ sw];
        float4 f2 = fp2[k4 ^ sw];
        float4 f3 = fp3[k4 ^ sw];
        #pragma unroll
        for (int i = 0; i < 4; i++) {
            float4 w = sW2[(k4 * 4 + i) * 8 + cg];
            float c0 = (i == 0) ? f0.x : (i == 1) ? f0.y : (i == 2) ? f0.z : f0.w;
            float c1 = (i == 0) ? f1.x : (i == 1) ? f1.y : (i == 2) ? f1.z : f1.w;
            float c2 = (i == 0) ? f2.x : (i == 1) ? f2.y : (i == 2) ? f2.z : f2.w;
            float c3 = (i == 0) ? f3.x : (i == 1) ? f3.y : (i == 2) ? f3.z : f3.w;
            a0.x += c0*w.x; a0.y += c0*w.y; a0.z += c0*w.z; a0.w += c0*w.w;
            a1.x += c1*w.x; a1.y += c1*w.y; a1.z += c1*w.z; a1.w += c1*w.w;
            a2.x += c2*w.x; a2.y += c2*w.y; a2.z += c2*w.z; a2.w += c2*w.w;
            a3.x += c3*w.x; a3.y += c3*w.y; a3.z += c3*w.z; a3.w += c3*w.w;
        }
    }

    #pragma unroll
    for (int j = 0; j < 4; j++) {
        int gr = row0 + rt + 32 * j;
        if (gr < n) {
            float ns = g_norm_out[gr];
            float4 a = (j == 0) ? a0 : (j == 1) ? a1 : (j == 2) ? a2 : a3;
            a.x *= ns; a.y *= ns; a.z *= ns; a.w *= ns;
            g_h[gr * 8 + cg] = a;
        }
    }
}

// ---------------------------------------------------------------- output
__global__ void out_kernel(const float* __restrict__ b2,
                           float* __restrict__ out, int n) {
    int idx = blockIdx.x * blockDim.x + threadIdx.x;
    if (idx >= n * 8) return;
    int row = idx >> 3, q = idx & 7;
    float4 v = *(const float4*)&g_agg2[row * 32 + q * 4];
    float ni = g_norm_in[row];
    float4 b = *(const float4*)&b2[q * 4];
    v.x = v.x * ni + b.x;
    v.y = v.y * ni + b.y;
    v.z = v.z * ni + b.z;
    v.w = v.w * ni + b.w;
    *(float4*)&out[row * 32 + q * 4] = v;
}

// ---------------------------------------------------------------- launch
namespace {
struct Ctx {
    cudaStream_t side;
    cudaEvent_t eFork, eJoin;
    Ctx() {
        cudaStreamCreateWithFlags(&side, cudaStreamNonBlocking);
        cudaEventCreateWithFlags(&eFork, cudaEventDisableTiming);
        cudaEventCreateWithFlags(&eJoin, cudaEventDisableTiming);
        cudaFuncSetAttribute(gemm1_kernel,
                             cudaFuncAttributeMaxDynamicSharedMemorySize, 81920);
    }
};
}

extern "C" void kernel_launch(void* const* d_in, const int* in_sizes, int n_in,
                              void* d_out, int out_size) {
    static Ctx ctx;   // resource init only (streams/events/attr), no cached work

    const float* feat = (const float*)d_in[0];
    const float* W1   = (const float*)d_in[1];
    const float* b1   = (const float*)d_in[2];
    const float* W2   = (const float*)d_in[3];
    const float* b2   = (const float*)d_in[4];
    const int*   src  = (const int*)d_in[5];
    const int*   dst  = (const int*)d_in[6];
    float* out = (float*)d_out;

    int n = in_sizes[0] / 128;
    int E = in_sizes[5];

    const int B = 256;
    long ethreads = (long)E * 8;
    int eblocks = (int)((ethreads + B - 1) / B);
    int gblocks = (n + 127) / 128;

    // Fork: gemm1 (independent of degrees) on side stream.
    cudaEventRecord(ctx.eFork, 0);
    cudaStreamWaitEvent(ctx.side, ctx.eFork, 0);
    gemm1_kernel<<<gblocks, 256, 81920, ctx.side>>>(feat, W1, n);
    cudaEventRecord(ctx.eJoin, ctx.side);

    // Main stream: zero + degree + norm chain (hidden under gemm1).
    zero_kernel   <<<(n * 8 + B - 1) / B, B>>>(n);
    degree_kernel <<<(E + B - 1) / B, B>>>(src, dst, E);
    norm_kernel   <<<(n + B - 1) / B, B>>>(n);

    // Join, then apply norm_out to h.
    cudaStreamWaitEvent(0, ctx.eJoin, 0);
    scale_h_kernel<<<(n * 8 + B - 1) / B, B>>>(n);

    edge_kernel<0><<<eblocks, B>>>(src, dst, E);
    mid_kernel    <<<gblocks, 256>>>(b1, W2, n);
    edge_kernel<1><<<eblocks, B>>>(src, dst, E);
    out_kernel    <<<(n * 8 + B - 1) / B, B>>>(b2, out, n);
}

// round 5
// speedup vs baseline: 1.8948x; 1.2058x over previous
#include <cuda_runtime.h>
#include <cuda_bf16.h>

// GCN: 2-layer graph conv, N=100000, E=1.6M, 128 -> 32 -> 32.
// Round 5: CSR build (once) + atomic-free GATHER aggregation (twice).
//   side stream : gemm1 (feat @ W1 -> g_h, unscaled)
//   main stream : zero -> int degrees -> norms -> 3-kernel scan -> CSR scatter
//   join        : scale_h (h *= norm_out)
//   gather<0>   : g_t = relu((sum h[src]) * norm_in + b1)      (g_t ref'd in DEVICE code)
//   mid GEMM    : g_h = (g_t @ W2) * norm_out
//   gather<1>   : d_out = (sum h[src]) * norm_in + b2
// NOTE: __device__ symbols are never passed as kernel args from host (round-4 bug).

#define MAXN 100000
#define MAXE 1600000
#define SCAN_B 512

__device__ int    g_deg_out[MAXN];
__device__ int    g_deg_in[MAXN];
__device__ float  g_norm_out[MAXN];
__device__ float  g_norm_in[MAXN];
__device__ int    g_offset[MAXN];      // exclusive prefix of deg_in
__device__ int    g_cursor[MAXN];      // scatter cursors
__device__ int    g_csr[MAXE];         // src ids grouped by dst
__device__ int    g_blocksums[(MAXN + SCAN_B - 1) / SCAN_B];
__device__ float4 g_h[MAXN * 8];       // projected features (pre-scaled by norm_out)
__device__ float4 g_t[MAXN * 8];       // layer-1 activations

// ---------------------------------------------------------------- zero
__global__ void zero_kernel(int n) {
    int i = blockIdx.x * blockDim.x + threadIdx.x;
    if (i < n) { g_deg_out[i] = 0; g_deg_in[i] = 0; g_cursor[i] = 0; }
}

// ---------------------------------------------------------------- degrees (int)
__global__ void degree_kernel(const int* __restrict__ src,
                              const int* __restrict__ dst, int E) {
    int e = blockIdx.x * blockDim.x + threadIdx.x;
    if (e < E) {
        atomicAdd(&g_deg_out[src[e]], 1);
        atomicAdd(&g_deg_in[dst[e]], 1);
    }
}

// ---------------------------------------------------------------- norms
__global__ void norm_kernel(int n) {
    int i = blockIdx.x * blockDim.x + threadIdx.x;
    if (i < n) {
        g_norm_out[i] = rsqrtf(fmaxf((float)g_deg_out[i], 1.f));
        g_norm_in[i]  = rsqrtf(fmaxf((float)g_deg_in[i], 1.f));
    }
}

// ---------------------------------------------------------------- scan A: per-block exclusive scan
__global__ __launch_bounds__(SCAN_B) void scanA_kernel(int n) {
    __shared__ int swarp[16];
    int t = threadIdx.x;
    int i = blockIdx.x * SCAN_B + t;
    int v = (i < n) ? g_deg_in[i] : 0;
    int lane = t & 31, w = t >> 5;
    int x = v;
    #pragma unroll
    for (int d = 1; d < 32; d <<= 1) {
        int y = __shfl_up_sync(0xffffffffu, x, d);
        if (lane >= d) x += y;
    }
    if (lane == 31) swarp[w] = x;
    __syncthreads();
    if (w == 0 && t < 16) {
        int y = swarp[t];
        #pragma unroll
        for (int d = 1; d < 16; d <<= 1) {
            int z = __shfl_up_sync(0xffffu, y, d);
            if (t >= d) y += z;
        }
        swarp[t] = y;
    }
    __syncthreads();
    int base = (w > 0) ? swarp[w - 1] : 0;
    int incl = x + base;
    if (i < n) g_offset[i] = incl - v;            // exclusive within block
    if (t == SCAN_B - 1) g_blocksums[blockIdx.x] = incl;
}

// ---------------------------------------------------------------- scan B: scan block sums (nb <= 256)
__global__ __launch_bounds__(256) void scanB_kernel(int nb) {
    __shared__ int swarp[8];
    int t = threadIdx.x;
    int v = (t < nb) ? g_blocksums[t] : 0;
    int lane = t & 31, w = t >> 5;
    int x = v;
    #pragma unroll
    for (int d = 1; d < 32; d <<= 1) {
        int y = __shfl_up_sync(0xffffffffu, x, d);
        if (lane >= d) x += y;
    }
    if (lane == 31) swarp[w] = x;
    __syncthreads();
    if (w == 0 && t < 8) {
        int y = swarp[t];
        #pragma unroll
        for (int d = 1; d < 8; d <<= 1) {
            int z = __shfl_up_sync(0xffu, y, d);
            if (t >= d) y += z;
        }
        swarp[t] = y;
    }
    __syncthreads();
    int base = (w > 0) ? swarp[w - 1] : 0;
    if (t < nb) g_blocksums[t] = x + base - v;    // exclusive
}

// ---------------------------------------------------------------- scan C: add block offsets
__global__ void scanC_kernel(int n) {
    int i = blockIdx.x * blockDim.x + threadIdx.x;
    if (i < n) g_offset[i] += g_blocksums[i / SCAN_B];
}

// ---------------------------------------------------------------- CSR scatter
__global__ void scatter_kernel(const int* __restrict__ src,
                               const int* __restrict__ dst, int E) {
    int e = blockIdx.x * blockDim.x + threadIdx.x;
    if (e < E) {
        int d = dst[e];
        int p = atomicAdd(&g_cursor[d], 1);
        g_csr[g_offset[d] + p] = src[e];
    }
}

// ---------------------------------------------------------------- GEMM1 (feat @ W1)
// 256 threads, 128 rows x 32 cols per block, 4 rows/thread; 80KB dyn smem.
__global__ __launch_bounds__(256) void gemm1_kernel(const float* __restrict__ feat,
                                                    const float* __restrict__ W1, int n) {
    extern __shared__ float4 dyn[];
    float4* sW = dyn;            // [k=128][cg=8]
    float4* sF = dyn + 1024;     // [row=128][k4=32] swizzled
    int t = threadIdx.x;

    for (int i = t; i < 1024; i += 256) sW[i] = ((const float4*)W1)[i];
    int row0 = blockIdx.x * 128;
    #pragma unroll
    for (int j = 0; j < 16; j++) {
        int i = t + j * 256;
        int r = i >> 5, k4 = i & 31;
        int gr = row0 + r;
        float4 v = make_float4(0.f, 0.f, 0.f, 0.f);
        if (gr < n) v = ((const float4*)feat)[gr * 32 + k4];
        sF[r * 32 + (k4 ^ (r & 7))] = v;
    }
    __syncthreads();

    int rt = t >> 3, cg = t & 7;
    int sw = rt & 7;
    const float4* fp0 = &sF[(rt +  0) * 32];
    const float4* fp1 = &sF[(rt + 32) * 32];
    const float4* fp2 = &sF[(rt + 64) * 32];
    const float4* fp3 = &sF[(rt + 96) * 32];

    float4 a0 = make_float4(0.f,0.f,0.f,0.f), a1 = a0, a2 = a0, a3 = a0;

    #pragma unroll 4
    for (int k4 = 0; k4 < 32; k4++) {
        float4 f0 = fp0[k4 ^ sw];
        float4 f1 = fp1[k4 ^ sw];
        float4 f2 = fp2[k4 ^ sw];
        float4 f3 = fp3[k4 ^ sw];
        #pragma unroll
        for (int i = 0; i < 4; i++) {
            float4 w = sW[(k4 * 4 + i) * 8 + cg];
            float c0 = (i == 0) ? f0.x : (i == 1) ? f0.y : (i == 2) ? f0.z : f0.w;
            float c1 = (i == 0) ? f1.x : (i == 1) ? f1.y : (i == 2) ? f1.z : f1.w;
            float c2 = (i == 0) ? f2.x : (i == 1) ? f2.y : (i == 2) ? f2.z : f2.w;
            float c3 = (i == 0) ? f3.x : (i == 1) ? f3.y : (i == 2) ? f3.z : f3.w;
            a0.x += c0*w.x; a0.y += c0*w.y; a0.z += c0*w.z; a0.w += c0*w.w;
            a1.x += c1*w.x; a1.y += c1*w.y; a1.z += c1*w.z; a1.w += c1*w.w;
            a2.x += c2*w.x; a2.y += c2*w.y; a2.z += c2*w.z; a2.w += c2*w.w;
            a3.x += c3*w.x; a3.y += c3*w.y; a3.z += c3*w.z; a3.w += c3*w.w;
        }
    }

    int gr;
    gr = row0 + rt;      if (gr < n) g_h[gr * 8 + cg] = a0;
    gr = row0 + rt + 32; if (gr < n) g_h[gr * 8 + cg] = a1;
    gr = row0 + rt + 64; if (gr < n) g_h[gr * 8 + cg] = a2;
    gr = row0 + rt + 96; if (gr < n) g_h[gr * 8 + cg] = a3;
}

// ---------------------------------------------------------------- scale h by norm_out
__global__ void scale_h_kernel(int n) {
    int i = blockIdx.x * blockDim.x + threadIdx.x;
    if (i >= n * 8) return;
    float s = g_norm_out[i >> 3];
    float4 v = g_h[i];
    v.x *= s; v.y *= s; v.z *= s; v.w *= s;
    g_h[i] = v;
}

// ---------------------------------------------------------------- gather aggregation
// 8 threads per dst node; acc = sum over incoming edges of g_h[src].
// LAYER 0: g_t[d] = relu(acc*norm_in + b1)   (g_t referenced in device code only)
// LAYER 1: outp[d] = acc*norm_in + b2        (outp = d_out, passed from harness)
template <int LAYER>
__global__ __launch_bounds__(256) void gather_kernel(const float* __restrict__ bias,
                                                     float4* __restrict__ outp, int n) {
    int tid = blockIdx.x * blockDim.x + threadIdx.x;
    int d = tid >> 3;
    if (d >= n) return;
    int q = tid & 7;
    int j = g_offset[d];
    int e = j + g_deg_in[d];

    float4 acc = make_float4(0.f, 0.f, 0.f, 0.f);
    for (; j + 1 < e; j += 2) {
        int s0 = __ldg(&g_csr[j]);
        int s1 = __ldg(&g_csr[j + 1]);
        float4 v0 = g_h[s0 * 8 + q];
        float4 v1 = g_h[s1 * 8 + q];
        acc.x += v0.x + v1.x;
        acc.y += v0.y + v1.y;
        acc.z += v0.z + v1.z;
        acc.w += v0.w + v1.w;
    }
    if (j < e) {
        int s0 = __ldg(&g_csr[j]);
        float4 v0 = g_h[s0 * 8 + q];
        acc.x += v0.x; acc.y += v0.y; acc.z += v0.z; acc.w += v0.w;
    }

    float ni = g_norm_in[d];
    float4 b = ((const float4*)bias)[q];
    acc.x = acc.x * ni + b.x;
    acc.y = acc.y * ni + b.y;
    acc.z = acc.z * ni + b.z;
    acc.w = acc.w * ni + b.w;
    if (LAYER == 0) {
        acc.x = fmaxf(acc.x, 0.f);
        acc.y = fmaxf(acc.y, 0.f);
        acc.z = fmaxf(acc.z, 0.f);
        acc.w = fmaxf(acc.w, 0.f);
        g_t[d * 8 + q] = acc;       // device symbol used from device code: OK
    } else {
        outp[d * 8 + q] = acc;      // d_out
    }
}

// ---------------------------------------------------------------- mid GEMM
// g_h = (g_t @ W2) * norm_out.   128 rows/block, 4 rows/thread, k=32.
__global__ __launch_bounds__(256) void mid_kernel(const float* __restrict__ W2, int n) {
    __shared__ float4 sW2[32 * 8];    // [k=32][cg=8]
    __shared__ float4 sT[128 * 8];    // [row=128][k4=8] swizzled
    int t = threadIdx.x;
    if (t < 256) sW2[t] = ((const float4*)W2)[t];
    int row0 = blockIdx.x * 128;
    #pragma unroll
    for (int j = 0; j < 4; j++) {
        int i = t + j * 256;
        int r = i >> 3, k4 = i & 7;
        int gr = row0 + r;
        float4 v = make_float4(0.f, 0.f, 0.f, 0.f);
        if (gr < n) v = g_t[gr * 8 + k4];
        sT[r * 8 + (k4 ^ (r & 7))] = v;
    }
    __syncthreads();

    int rt = t >> 3, cg = t & 7;
    int sw = rt & 7;
    const float4* fp0 = &sT[(rt +  0) * 8];
    const float4* fp1 = &sT[(rt + 32) * 8];
    const float4* fp2 = &sT[(rt + 64) * 8];
    const float4* fp3 = &sT[(rt + 96) * 8];

    float4 a0 = make_float4(0.f,0.f,0.f,0.f), a1 = a0, a2 = a0, a3 = a0;

    #pragma unroll
    for (int k4 = 0; k4 < 8; k4++) {
        float4 f0 = fp0[k4 ^ sw];
        float4 f1 = fp1[k4 ^ sw];
        float4 f2 = fp2[k4 ^ sw];
        float4 f3 = fp3[k4 ^ sw];
        #pragma unroll
        for (int i = 0; i < 4; i++) {
            float4 w = sW2[(k4 * 4 + i) * 8 + cg];
            float c0 = (i == 0) ? f0.x : (i == 1) ? f0.y : (i == 2) ? f0.z : f0.w;
            float c1 = (i == 0) ? f1.x : (i == 1) ? f1.y : (i == 2) ? f1.z : f1.w;
            float c2 = (i == 0) ? f2.x : (i == 1) ? f2.y : (i == 2) ? f2.z : f2.w;
            float c3 = (i == 0) ? f3.x : (i == 1) ? f3.y : (i == 2) ? f3.z : f3.w;
            a0.x += c0*w.x; a0.y += c0*w.y; a0.z += c0*w.z; a0.w += c0*w.w;
            a1.x += c1*w.x; a1.y += c1*w.y; a1.z += c1*w.z; a1.w += c1*w.w;
            a2.x += c2*w.x; a2.y += c2*w.y; a2.z += c2*w.z; a2.w += c2*w.w;
            a3.x += c3*w.x; a3.y += c3*w.y; a3.z += c3*w.z; a3.w += c3*w.w;
        }
    }

    #pragma unroll
    for (int j = 0; j < 4; j++) {
        int gr = row0 + rt + 32 * j;
        if (gr < n) {
            float ns = g_norm_out[gr];
            float4 a = (j == 0) ? a0 : (j == 1) ? a1 : (j == 2) ? a2 : a3;
            a.x *= ns; a.y *= ns; a.z *= ns; a.w *= ns;
            g_h[gr * 8 + cg] = a;
        }
    }
}

// ---------------------------------------------------------------- launch
namespace {
struct Ctx {
    cudaStream_t side;
    cudaEvent_t eFork, eJoin;
    Ctx() {
        cudaStreamCreateWithFlags(&side, cudaStreamNonBlocking);
        cudaEventCreateWithFlags(&eFork, cudaEventDisableTiming);
        cudaEventCreateWithFlags(&eJoin, cudaEventDisableTiming);
        cudaFuncSetAttribute(gemm1_kernel,
                             cudaFuncAttributeMaxDynamicSharedMemorySize, 81920);
    }
};
}

extern "C" void kernel_launch(void* const* d_in, const int* in_sizes, int n_in,
                              void* d_out, int out_size) {
    static Ctx ctx;   // resource init only (streams/events/attr), no cached work

    const float* feat = (const float*)d_in[0];
    const float* W1   = (const float*)d_in[1];
    const float* b1   = (const float*)d_in[2];
    const float* W2   = (const float*)d_in[3];
    const float* b2   = (const float*)d_in[4];
    const int*   src  = (const int*)d_in[5];
    const int*   dst  = (const int*)d_in[6];
    float4* out = (float4*)d_out;

    int n = in_sizes[0] / 128;
    int E = in_sizes[5];

    const int B = 256;
    int gblocks = (n + 127) / 128;
    int nb = (n + SCAN_B - 1) / SCAN_B;

    // Fork: gemm1 (independent of graph structure) on side stream.
    cudaEventRecord(ctx.eFork, 0);
    cudaStreamWaitEvent(ctx.side, ctx.eFork, 0);
    gemm1_kernel<<<gblocks, 256, 81920, ctx.side>>>(feat, W1, n);
    cudaEventRecord(ctx.eJoin, ctx.side);

    // Main stream: degrees -> norms -> scan -> CSR (hidden under gemm1).
    zero_kernel    <<<(n + B - 1) / B, B>>>(n);
    degree_kernel  <<<(E + B - 1) / B, B>>>(src, dst, E);
    norm_kernel    <<<(n + B - 1) / B, B>>>(n);
    scanA_kernel   <<<nb, SCAN_B>>>(n);
    scanB_kernel   <<<1, 256>>>(nb);
    scanC_kernel   <<<(n + B - 1) / B, B>>>(n);
    scatter_kernel <<<(E + B - 1) / B, B>>>(src, dst, E);

    // Join, then scale h by norm_out.
    cudaStreamWaitEvent(0, ctx.eJoin, 0);
    scale_h_kernel<<<(n * 8 + B - 1) / B, B>>>(n);

    gather_kernel<0><<<(n * 8 + B - 1) / B, B>>>(b1, out, n);  // writes g_t internally
    mid_kernel       <<<gblocks, 256>>>(W2, n);
    gather_kernel<1><<<(n * 8 + B - 1) / B, B>>>(b2, out, n);  // writes d_out
}